// round 9
// baseline (speedup 1.0000x reference)
#include <cuda_runtime.h>

// OHLCVPackedScaler — fused one-wave kernel (128 CTAs), per-batch barrier,
// REDG global accumulation (no phase-2 reduce loop), ballot dtype detection.

namespace {
constexpr int B_ = 4;
constexpr int S_ = 4096;
constexpr int D_ = 32;
constexpr int NG = 32;            // (sid 0..7) x (gid 0..3)
constexpr int NC = 32;            // chunks per batch
constexpr int CHUNK = S_ / NC;    // 128 tokens
constexpr int NT = 512;
constexpr int NCTA = B_ * NC;     // 128 (single wave)
constexpr int PAD = 64;           // counter padding (256B)
constexpr int ACCP = 128;         // per-batch accumulator stride (512B)
}

__device__ float g_acc[B_ * ACCP];           // [b][96 used] — zero at idle
__device__ unsigned int g_bar[B_ * PAD];     // per-batch barrier arrivals
__device__ unsigned int g_fin[B_ * PAD];     // per-batch exit arrivals

__global__ __launch_bounds__(NT, 1) void ohlcv_fused(
    const float* __restrict__ target,
    const void* __restrict__ obs,
    const int* __restrict__ sample_id,
    const int* __restrict__ variate_id,
    float* __restrict__ out)
{
    const int b = blockIdx.x / NC;
    const int c = blockIdx.x - b * NC;
    const int tid   = threadIdx.x;
    const int lane  = tid & 31;
    const int tok_l = tid >> 2;          // 0..127
    const int q     = tid & 3;           // quarter: dims q*8..q*8+7
    const int s     = c * CHUNK + tok_l; // token within batch

    // ---- issue ALL global loads up front (MLP ~8) ----
    const int sid = __ldg(sample_id + b * S_ + s);
    const int v   = __ldg(variate_id + b * S_ + s);

    const float4* tp = reinterpret_cast<const float4*>(
        target + (size_t)(b * S_ + s) * D_) + q * 2;
    float4 t0 = __ldg(tp);
    float4 t1 = __ldg(tp + 1);

    const size_t eoff = (size_t)(b * S_ + s) * D_ + q * 8;   // element offset
    // byte interpretation (bool mask)
    uint2 mb = __ldg(reinterpret_cast<const uint2*>(
                     (const unsigned char*)obs + eoff));
    // word interpretation (int32 OR float32: both are "bits != 0"; 1.0f has
    // nonzero bits, 0.0f is all-zero — masks are never -0.0f)
    const uint4* mwp = reinterpret_cast<const uint4*>(
                       (const unsigned int*)obs + eoff);
    uint4 mw0 = __ldg(mwp);
    uint4 mw1 = __ldg(mwp + 1);

    // ---- warp-local dtype detection from first 256B (L1 broadcast) ----
    bool big = false, nb = false;
    {
        uint4 x = __ldg(reinterpret_cast<const uint4*>(obs) + (lane & 15));
        unsigned mx = max(max(x.x, x.y), max(x.z, x.w));
        big = mx > 0x01010101u;
        nb  = mx > 1u;
    }
    const unsigned any_big = __ballot_sync(0xFFFFFFFFu, big);
    const unsigned any_nb  = __ballot_sync(0xFFFFFFFFu, nb);
    const bool is_bytes = (any_big == 0u) && (any_nb != 0u);

    // ---- weights ----
    float w[8];
    if (is_bytes) {
        w[0] = (mb.x & 0x000000FFu) ? 1.f : 0.f;
        w[1] = (mb.x & 0x0000FF00u) ? 1.f : 0.f;
        w[2] = (mb.x & 0x00FF0000u) ? 1.f : 0.f;
        w[3] = (mb.x & 0xFF000000u) ? 1.f : 0.f;
        w[4] = (mb.y & 0x000000FFu) ? 1.f : 0.f;
        w[5] = (mb.y & 0x0000FF00u) ? 1.f : 0.f;
        w[6] = (mb.y & 0x00FF0000u) ? 1.f : 0.f;
        w[7] = (mb.y & 0xFF000000u) ? 1.f : 0.f;
    } else {
        w[0] = mw0.x ? 1.f : 0.f;  w[1] = mw0.y ? 1.f : 0.f;
        w[2] = mw0.z ? 1.f : 0.f;  w[3] = mw0.w ? 1.f : 0.f;
        w[4] = mw1.x ? 1.f : 0.f;  w[5] = mw1.y ? 1.f : 0.f;
        w[6] = mw1.z ? 1.f : 0.f;  w[7] = mw1.w ? 1.f : 0.f;
    }

    const int grp = sid * 4 + ((v < 4) ? 0 : (v - 3));

    float t[8] = {t0.x, t0.y, t0.z, t0.w, t1.x, t1.y, t1.z, t1.w};
    float n = 0.f, sm = 0.f, qq = 0.f;
    #pragma unroll
    for (int i = 0; i < 8; i++) {
        n  += w[i];
        sm += w[i] * t[i];
        qq += w[i] * t[i] * t[i];
    }

    // combine 4 quarters of a token
    n  += __shfl_xor_sync(0xFFFFFFFFu, n,  1);
    sm += __shfl_xor_sync(0xFFFFFFFFu, sm, 1);
    qq += __shfl_xor_sync(0xFFFFFFFFu, qq, 1);
    n  += __shfl_xor_sync(0xFFFFFFFFu, n,  2);
    sm += __shfl_xor_sync(0xFFFFFFFFu, sm, 2);
    qq += __shfl_xor_sync(0xFFFFFFFFu, qq, 2);

    __shared__ float acc[NG * 3];
    __shared__ int   sgrp[CHUNK];
    __shared__ float red[NG * 3];
    __shared__ float ls[NG][2];

    if (tid < NG * 3) acc[tid] = 0.f;
    __syncthreads();

    if (q == 0) {
        sgrp[tok_l] = grp;
        atomicAdd(&acc[grp * 3 + 0], n);
        atomicAdd(&acc[grp * 3 + 1], sm);
        atomicAdd(&acc[grp * 3 + 2], qq);
    }
    __syncthreads();

    // ---- REDG accumulate this CTA's partials into per-batch slots ----
    if (tid < NG * 3)
        atomicAdd(&g_acc[b * ACCP + tid], acc[tid]);   // return unused -> RED
    __threadfence();
    __syncthreads();

    // ---- per-batch barrier: 32 arrivals, hard spin poll ----
    if (tid == 0) {
        atomicAdd(&g_bar[b * PAD], 1u);
        volatile unsigned int* pc = &g_bar[b * PAD];
        while (*pc < (unsigned)NC) { }
    }
    __syncthreads();
    __threadfence();

    // ---- read final sums (L2-fresh) and finalize ----
    if (tid < NG * 3)
        red[tid] = *((volatile float*)&g_acc[b * ACCP + tid]);
    __syncthreads();

    if (tid < NG) {
        float N  = red[tid * 3 + 0];
        float SM = red[tid * 3 + 1];
        float Q  = red[tid * 3 + 2];
        // uni2ts safe_div: denom==0 -> divide by 1
        float dN  = (N == 0.f) ? 1.f : N;
        float loc = SM / dN;
        float vs  = fmaxf(Q - 2.f * loc * SM + loc * loc * N, 0.f);
        float dC  = N - 1.f;
        if (dC == 0.f) dC = 1.f;
        float scale = sqrtf(vs / dC + 1e-5f);
        if ((tid >> 2) == 0) { loc = 0.f; scale = 1.f; }   // sid==0 padding
        ls[tid][0] = loc;
        ls[tid][1] = scale;
    }
    __syncthreads();

    // ---- scatter this CTA's chunk: 128 loc + 128 scale words, coalesced ----
    if (tid < 2 * CHUNK) {
        const int which = tid >> 7;              // 0 = loc, 1 = scale
        const int tt    = tid & (CHUNK - 1);
        const int ss    = c * CHUNK + tt;
        const float val = ls[sgrp[tt]][which];
        float* dst = which ? (out + (size_t)B_ * S_ + (size_t)b * S_ + ss)
                           : (out + (size_t)b * S_ + ss);
        *dst = val;
    }
    __syncthreads();   // all reads of g_acc & scatter done before g_fin arrival

    // ---- per-batch reset for graph-replay safety ----
    // Last CTA of batch b zeroes its accumulators (all 32 CTAs have read them)
    // and resets counters. Kernel-completion ordering makes this visible to
    // the next replay.
    if (tid == 0) {
        unsigned r = atomicAdd(&g_fin[b * PAD], 1u);
        if (r == (unsigned)(NC - 1)) {
            #pragma unroll
            for (int i = 0; i < NG * 3; i++)
                g_acc[b * ACCP + i] = 0.f;
            atomicExch(&g_bar[b * PAD], 0u);
            atomicExch(&g_fin[b * PAD], 0u);
        }
    }
}

extern "C" void kernel_launch(void* const* d_in, const int* in_sizes, int n_in,
                              void* d_out, int out_size) {
    (void)in_sizes; (void)n_in; (void)out_size;
    const float* target     = (const float*)d_in[0];
    const void*  obs        = (const void*)d_in[1];
    const int*   sample_id  = (const int*)d_in[2];
    const int*   variate_id = (const int*)d_in[3];
    float*       out        = (float*)d_out;
    ohlcv_fused<<<NCTA, NT>>>(target, obs, sample_id, variate_id, out);
}

// round 10
// speedup vs baseline: 1.2250x; 1.2250x over previous
#include <cuda_runtime.h>

// OHLCVPackedScaler — fused one-wave kernel, NO grid barrier.
// Every CTA: dense chunk scan -> smem partials -> REDG into per-batch sums.
// The last-arriving CTA per batch finalizes loc/scale and writes the whole
// batch's output. All other CTAs exit immediately.

namespace {
constexpr int B_ = 4;
constexpr int S_ = 4096;
constexpr int D_ = 32;
constexpr int NG = 32;            // (sid 0..7) x (gid 0..3)
constexpr int NC = 32;            // chunks per batch
constexpr int CHUNK = S_ / NC;    // 128 tokens
constexpr int NT = 512;
constexpr int NCTA = B_ * NC;     // 128 (single wave)
constexpr int PAD = 64;           // counter padding (256B)
constexpr int ACCP = 128;         // per-batch accumulator stride (512B)
}

__device__ float g_acc[B_ * ACCP];           // [b][96 used] — zero at idle
__device__ unsigned int g_fin[B_ * PAD];     // per-batch arrival counters

__global__ __launch_bounds__(NT, 1) void ohlcv_fused(
    const float* __restrict__ target,
    const void* __restrict__ obs,
    const int* __restrict__ sample_id,
    const int* __restrict__ variate_id,
    float* __restrict__ out)
{
    const int b = blockIdx.x / NC;
    const int c = blockIdx.x - b * NC;
    const int tid   = threadIdx.x;
    const int lane  = tid & 31;
    const int tok_l = tid >> 2;          // 0..127
    const int q     = tid & 3;           // quarter: dims q*8..q*8+7
    const int s     = c * CHUNK + tok_l; // token within batch

    // ---- issue ALL global loads up front (MLP ~8) ----
    const int sid = __ldg(sample_id + b * S_ + s);
    const int v   = __ldg(variate_id + b * S_ + s);

    const float4* tp = reinterpret_cast<const float4*>(
        target + (size_t)(b * S_ + s) * D_) + q * 2;
    float4 t0 = __ldg(tp);
    float4 t1 = __ldg(tp + 1);

    const size_t eoff = (size_t)(b * S_ + s) * D_ + q * 8;   // element offset
    // byte interpretation (bool mask)
    uint2 mb = __ldg(reinterpret_cast<const uint2*>(
                     (const unsigned char*)obs + eoff));
    // word interpretation (int32 OR float32: both are "bits != 0")
    const uint4* mwp = reinterpret_cast<const uint4*>(
                       (const unsigned int*)obs + eoff);
    uint4 mw0 = __ldg(mwp);
    uint4 mw1 = __ldg(mwp + 1);

    // ---- warp-local dtype detection from first 256B (L1 broadcast) ----
    bool big = false, nb = false;
    {
        uint4 x = __ldg(reinterpret_cast<const uint4*>(obs) + (lane & 15));
        unsigned mx = max(max(x.x, x.y), max(x.z, x.w));
        big = mx > 0x01010101u;
        nb  = mx > 1u;
    }
    const unsigned any_big = __ballot_sync(0xFFFFFFFFu, big);
    const unsigned any_nb  = __ballot_sync(0xFFFFFFFFu, nb);
    const bool is_bytes = (any_big == 0u) && (any_nb != 0u);

    // ---- weights ----
    float w[8];
    if (is_bytes) {
        w[0] = (mb.x & 0x000000FFu) ? 1.f : 0.f;
        w[1] = (mb.x & 0x0000FF00u) ? 1.f : 0.f;
        w[2] = (mb.x & 0x00FF0000u) ? 1.f : 0.f;
        w[3] = (mb.x & 0xFF000000u) ? 1.f : 0.f;
        w[4] = (mb.y & 0x000000FFu) ? 1.f : 0.f;
        w[5] = (mb.y & 0x0000FF00u) ? 1.f : 0.f;
        w[6] = (mb.y & 0x00FF0000u) ? 1.f : 0.f;
        w[7] = (mb.y & 0xFF000000u) ? 1.f : 0.f;
    } else {
        w[0] = mw0.x ? 1.f : 0.f;  w[1] = mw0.y ? 1.f : 0.f;
        w[2] = mw0.z ? 1.f : 0.f;  w[3] = mw0.w ? 1.f : 0.f;
        w[4] = mw1.x ? 1.f : 0.f;  w[5] = mw1.y ? 1.f : 0.f;
        w[6] = mw1.z ? 1.f : 0.f;  w[7] = mw1.w ? 1.f : 0.f;
    }

    const int grp = sid * 4 + ((v < 4) ? 0 : (v - 3));

    float t[8] = {t0.x, t0.y, t0.z, t0.w, t1.x, t1.y, t1.z, t1.w};
    float n = 0.f, sm = 0.f, qq = 0.f;
    #pragma unroll
    for (int i = 0; i < 8; i++) {
        n  += w[i];
        sm += w[i] * t[i];
        qq += w[i] * t[i] * t[i];
    }

    // combine 4 quarters of a token
    n  += __shfl_xor_sync(0xFFFFFFFFu, n,  1);
    sm += __shfl_xor_sync(0xFFFFFFFFu, sm, 1);
    qq += __shfl_xor_sync(0xFFFFFFFFu, qq, 1);
    n  += __shfl_xor_sync(0xFFFFFFFFu, n,  2);
    sm += __shfl_xor_sync(0xFFFFFFFFu, sm, 2);
    qq += __shfl_xor_sync(0xFFFFFFFFu, qq, 2);

    __shared__ float acc[NG * 3];
    __shared__ float red[NG * 3];
    __shared__ float ls[NG][2];
    __shared__ int   s_last;

    if (tid < NG * 3) acc[tid] = 0.f;
    __syncthreads();

    if (q == 0) {
        atomicAdd(&acc[grp * 3 + 0], n);
        atomicAdd(&acc[grp * 3 + 1], sm);
        atomicAdd(&acc[grp * 3 + 2], qq);
    }
    __syncthreads();

    // ---- REDG accumulate this CTA's partials into per-batch slots ----
    if (tid < NG * 3)
        atomicAdd(&g_acc[b * ACCP + tid], acc[tid]);   // return unused -> RED
    if (tid < NG * 3)
        __threadfence();          // order my REDGs before the arrival below
    __syncthreads();

    // ---- last-CTA election (no waiting, no spin) ----
    if (tid == 0) {
        unsigned r = atomicAdd(&g_fin[b * PAD], 1u);
        s_last = (r == (unsigned)(NC - 1)) ? 1 : 0;
    }
    __syncthreads();

    if (!s_last) return;          // 31 of 32 CTAs per batch exit here

    // ================= finalizer: exactly one CTA per batch =================
    // All 32 CTAs' fences happened-before their g_fin arrivals; we observed
    // the 32nd arrival, so all REDGs are visible.
    if (tid < NG * 3) {
        float sum = *((volatile float*)&g_acc[b * ACCP + tid]);
        red[tid] = sum;
        g_acc[b * ACCP + tid] = 0.f;     // reset for next graph replay
    }
    if (tid == 0)
        g_fin[b * PAD] = 0u;             // sole toucher now; replay-safe
    __syncthreads();

    if (tid < NG) {
        float N  = red[tid * 3 + 0];
        float SM = red[tid * 3 + 1];
        float Q  = red[tid * 3 + 2];
        // uni2ts safe_div: denom==0 -> divide by 1
        float dN  = (N == 0.f) ? 1.f : N;
        float loc = SM / dN;
        float vs  = fmaxf(Q - 2.f * loc * SM + loc * loc * N, 0.f);
        float dC  = N - 1.f;
        if (dC == 0.f) dC = 1.f;
        float scale = sqrtf(vs / dC + 1e-5f);
        if ((tid >> 2) == 0) { loc = 0.f; scale = 1.f; }   // sid==0 padding
        ls[tid][0] = loc;
        ls[tid][1] = scale;
    }
    __syncthreads();

    // ---- write the ENTIRE batch's output (ids are L2-hot) ----
    float* __restrict__ out_loc = out + (size_t)b * S_;
    float* __restrict__ out_sc  = out + (size_t)B_ * S_ + (size_t)b * S_;
    const int* __restrict__ sb = sample_id  + b * S_;
    const int* __restrict__ vb = variate_id + b * S_;

    #pragma unroll
    for (int i = 0; i < S_ / NT; i++) {
        const int ss  = i * NT + tid;
        const int sd  = __ldg(sb + ss);
        const int vv  = __ldg(vb + ss);
        const int g   = sd * 4 + ((vv < 4) ? 0 : (vv - 3));
        out_loc[ss] = ls[g][0];
        out_sc[ss]  = ls[g][1];
    }
}

extern "C" void kernel_launch(void* const* d_in, const int* in_sizes, int n_in,
                              void* d_out, int out_size) {
    (void)in_sizes; (void)n_in; (void)out_size;
    const float* target     = (const float*)d_in[0];
    const void*  obs        = (const void*)d_in[1];
    const int*   sample_id  = (const int*)d_in[2];
    const int*   variate_id = (const int*)d_in[3];
    float*       out        = (float*)d_out;
    ohlcv_fused<<<NCTA, NT>>>(target, obs, sample_id, variate_id, out);
}